// round 1
// baseline (speedup 1.0000x reference)
#include <cuda_runtime.h>

// Problem constants (fixed by the reference)
#define BB    64
#define TT    512
#define D_IN  512
#define D_HID 1024
#define D_OUT 512
#define EPS_  1e-5f

// Scratch for the hidden activation h = relu(x@W1+b1): [B, T, D_HID] fp32 = 128 MB.
// Static __device__ array — no runtime allocation (harness rule).
__device__ float g_h[(size_t)BB * TT * D_HID];

// ----------------------------------------------------------------------------
// Register-blocked 64x64 tile GEMM, per-sample weight selection by day index.
//   C[b] = act(A[b] @ W[day[b]] + bias[day[b]])
// A: [B, T, K] row-major, W: [24, K, N] row-major, bias: [24, N]
// Block: 256 threads, each computes 4x4 outputs. K-tile = 16.
// ----------------------------------------------------------------------------
template<int K, int N, bool RELU>
__global__ __launch_bounds__(256) void gemm_day_kernel(
    const float* __restrict__ A,
    const float* __restrict__ W,
    const float* __restrict__ bias,
    const int*   __restrict__ day,
    float*       __restrict__ C)
{
    const int b       = blockIdx.x;
    const int rowBase = blockIdx.y * 64;
    const int colBase = blockIdx.z * 64;
    const int d       = day[b];

    const float* Ab = A + (size_t)b * TT * K;
    const float* Wd = W + (size_t)d * K * N;

    // As stored K-major (transposed) so the inner loop reads contiguous float4s.
    __shared__ float As[16][64];
    __shared__ float Bs[16][64];

    const int tid  = threadIdx.x;
    const int trow = tid >> 4;   // 0..15 -> output rows trow*4 .. +3
    const int tcol = tid & 15;   // 0..15 -> output cols tcol*4 .. +3

    // global->shared load mapping
    const int ar = tid >> 2;        // 0..63  (A row within tile)
    const int ac = (tid & 3) * 4;   // 0,4,8,12 (A k-offset within tile)
    const int bk = tid >> 4;        // 0..15  (B k within tile)
    const int bn = (tid & 15) * 4;  // 0..60  (B col within tile)

    float acc[4][4] = {};

    for (int k0 = 0; k0 < K; k0 += 16) {
        const float4 av = *(const float4*)(Ab + (size_t)(rowBase + ar) * K + k0 + ac);
        const float4 bv = *(const float4*)(Wd + (size_t)(k0 + bk) * N + colBase + bn);
        __syncthreads();   // previous iteration's reads complete before overwrite
        As[ac + 0][ar] = av.x;
        As[ac + 1][ar] = av.y;
        As[ac + 2][ar] = av.z;
        As[ac + 3][ar] = av.w;
        *(float4*)&Bs[bk][bn] = bv;
        __syncthreads();

        #pragma unroll
        for (int k = 0; k < 16; k++) {
            const float4 a4 = *(const float4*)&As[k][trow * 4];
            const float4 b4 = *(const float4*)&Bs[k][tcol * 4];
            const float areg[4] = {a4.x, a4.y, a4.z, a4.w};
            const float breg[4] = {b4.x, b4.y, b4.z, b4.w};
            #pragma unroll
            for (int i = 0; i < 4; i++)
                #pragma unroll
                for (int j = 0; j < 4; j++)
                    acc[i][j] = fmaf(areg[i], breg[j], acc[i][j]);
        }
    }

    const float* biasd = bias + (size_t)d * N;
    float* Cb = C + (size_t)b * TT * N;
    const float4 bias4 = *(const float4*)(biasd + colBase + tcol * 4);
    const float bsel[4] = {bias4.x, bias4.y, bias4.z, bias4.w};

    #pragma unroll
    for (int i = 0; i < 4; i++) {
        const int r = rowBase + trow * 4 + i;
        float4 o;
        float* op = &o.x;
        #pragma unroll
        for (int j = 0; j < 4; j++) {
            float v = acc[i][j] + bsel[j];
            if (RELU) v = fmaxf(v, 0.0f);
            op[j] = v;
        }
        *(float4*)&Cb[(size_t)r * N + colBase + tcol * 4] = o;
    }
}

// ----------------------------------------------------------------------------
// In-place LayerNorm over last dim (512) + per-day affine.
// One block (256 threads) per (b, t) row; each thread handles 2 elements.
// ----------------------------------------------------------------------------
__global__ __launch_bounds__(256) void ln_kernel(
    float*       __restrict__ y,      // [B*T, D_OUT], in-place
    const float* __restrict__ gamma,  // [24, D_OUT]
    const float* __restrict__ beta,   // [24, D_OUT]
    const int*   __restrict__ day)
{
    const int row = blockIdx.x;          // b*T + t
    const int b   = row / TT;
    const int d   = day[b];
    float* yr = y + (size_t)row * D_OUT;

    const int tid = threadIdx.x;         // 0..255
    const float2 v = *(const float2*)(yr + tid * 2);

    float s  = v.x + v.y;
    float sq = v.x * v.x + v.y * v.y;

    #pragma unroll
    for (int off = 16; off; off >>= 1) {
        s  += __shfl_xor_sync(0xffffffffu, s,  off);
        sq += __shfl_xor_sync(0xffffffffu, sq, off);
    }

    __shared__ float ss[8], sqs[8];
    const int w = tid >> 5, l = tid & 31;
    if (l == 0) { ss[w] = s; sqs[w] = sq; }
    __syncthreads();
    if (w == 0) {
        s  = (l < 8) ? ss[l]  : 0.0f;
        sq = (l < 8) ? sqs[l] : 0.0f;
        #pragma unroll
        for (int off = 16; off; off >>= 1) {
            s  += __shfl_xor_sync(0xffffffffu, s,  off);
            sq += __shfl_xor_sync(0xffffffffu, sq, off);
        }
        if (l == 0) { ss[0] = s; sqs[0] = sq; }
    }
    __syncthreads();
    s  = ss[0];
    sq = sqs[0];

    const float mean = s * (1.0f / D_OUT);
    const float var  = sq * (1.0f / D_OUT) - mean * mean;
    const float inv  = rsqrtf(var + EPS_);

    const float2 g2 = *(const float2*)(gamma + (size_t)d * D_OUT + tid * 2);
    const float2 b2 = *(const float2*)(beta  + (size_t)d * D_OUT + tid * 2);
    float2 o;
    o.x = (v.x - mean) * inv * g2.x + b2.x;
    o.y = (v.y - mean) * inv * g2.y + b2.y;
    *(float2*)(yr + tid * 2) = o;
}

extern "C" void kernel_launch(void* const* d_in, const int* in_sizes, int n_in,
                              void* d_out, int out_size)
{
    // metadata order: x, day_indices, W1, b1, W2, b2, gamma, beta
    const float* x     = (const float*)d_in[0];
    const int*   day   = (const int*)  d_in[1];
    const float* W1    = (const float*)d_in[2];
    const float* b1    = (const float*)d_in[3];
    const float* W2    = (const float*)d_in[4];
    const float* b2    = (const float*)d_in[5];
    const float* gamma = (const float*)d_in[6];
    const float* beta  = (const float*)d_in[7];
    float* out = (float*)d_out;

    float* h;
    cudaGetSymbolAddress((void**)&h, g_h);

    // GEMM1: [T=512, K=512] @ [512, 1024] -> h, relu
    dim3 g1(BB, TT / 64, D_HID / 64);
    gemm_day_kernel<D_IN, D_HID, true><<<g1, 256>>>(x, W1, b1, day, h);

    // GEMM2: [T=512, K=1024] @ [1024, 512] -> out (pre-LN y)
    dim3 g2(BB, TT / 64, D_OUT / 64);
    gemm_day_kernel<D_HID, D_OUT, false><<<g2, 256>>>(h, W2, b2, day, out);

    // LayerNorm + per-day affine, in-place on out
    ln_kernel<<<BB * TT, 256>>>(out, gamma, beta, day);
}

// round 4
// speedup vs baseline: 4.4454x; 4.4454x over previous
#include <cuda_runtime.h>
#include <cstdint>

#define BB    64
#define TT    512
#define DIN   512
#define DHID  1024
#define DOUT  512
#define NDAYS 24
#define EPS_  1e-5f

// Scratch (__device__ globals; no runtime allocation).
__device__ float g_xt [(size_t)BB * TT * DIN];       //  64 MB  x, RNA->tf32
__device__ float g_h  [(size_t)BB * TT * DHID];      // 128 MB  hidden
__device__ float g_wt1[(size_t)NDAYS * DHID * DIN];  //  48 MB  W1^T [d][n][k]
__device__ float g_wt2[(size_t)NDAYS * DOUT * DHID]; //  48 MB  W2^T [d][n][k]

// ---------------------------------------------------------------- helpers
__device__ __forceinline__ float rna_tf32(float x) {
    // NOTE: tf32 cvt destination must be a .b32 register (ptxas rejects .f32)
    uint32_t r;
    asm("cvt.rna.tf32.f32 %0, %1;" : "=r"(r) : "f"(x));
    return __uint_as_float(r);
}
__device__ __forceinline__ uint32_t smem_u32(const void* p) {
    uint32_t a;
    asm("{ .reg .u64 t; cvta.to.shared.u64 t, %1; cvt.u32.u64 %0, t; }"
        : "=r"(a) : "l"(p));
    return a;
}
__device__ __forceinline__ void cp16(uint32_t dst, const void* src) {
    asm volatile("cp.async.cg.shared.global [%0], [%1], 16;"
                 :: "r"(dst), "l"(src) : "memory");
}
__device__ __forceinline__ void ldm4(uint32_t& r0, uint32_t& r1,
                                     uint32_t& r2, uint32_t& r3, uint32_t a) {
    asm volatile("ldmatrix.sync.aligned.m8n8.x4.shared.b16 {%0,%1,%2,%3}, [%4];"
                 : "=r"(r0), "=r"(r1), "=r"(r2), "=r"(r3) : "r"(a));
}
__device__ __forceinline__ void mma1688(float* c, const uint32_t* a,
                                        uint32_t b0, uint32_t b1) {
    asm volatile(
        "mma.sync.aligned.m16n8k8.row.col.f32.tf32.tf32.f32 "
        "{%0,%1,%2,%3}, {%4,%5,%6,%7}, {%8,%9}, {%0,%1,%2,%3};"
        : "+f"(c[0]), "+f"(c[1]), "+f"(c[2]), "+f"(c[3])
        : "r"(a[0]), "r"(a[1]), "r"(a[2]), "r"(a[3]), "r"(b0), "r"(b1));
}

// ---------------------------------------------------------------- prep passes
__global__ __launch_bounds__(256) void cvt_x_kernel(const float4* __restrict__ in,
                                                    float4* __restrict__ out, int n4) {
    int i = blockIdx.x * blockDim.x + threadIdx.x;
    if (i < n4) {
        float4 v = in[i];
        v.x = rna_tf32(v.x); v.y = rna_tf32(v.y);
        v.z = rna_tf32(v.z); v.w = rna_tf32(v.w);
        out[i] = v;
    }
}

// W [NDAYS][K][N] -> Wt [NDAYS][N][K], with RNA rounding.
template<int K, int N>
__global__ __launch_bounds__(256) void transpose_rna_kernel(const float* __restrict__ W,
                                                            float* __restrict__ Wt) {
    __shared__ float t[32][33];
    const int d  = blockIdx.z;
    const int n0 = blockIdx.x * 32;
    const int k0 = blockIdx.y * 32;
    const float* Wd  = W  + (size_t)d * K * N;
    float*       Wtd = Wt + (size_t)d * N * K;
    const int tx = threadIdx.x, ty = threadIdx.y;  // 32 x 8
    #pragma unroll
    for (int r = 0; r < 32; r += 8)
        t[ty + r][tx] = rna_tf32(Wd[(size_t)(k0 + ty + r) * N + n0 + tx]);
    __syncthreads();
    #pragma unroll
    for (int r = 0; r < 32; r += 8)
        Wtd[(size_t)(n0 + ty + r) * K + k0 + tx] = t[tx][ty + r];
}

// ---------------------------------------------------------------- TF32 GEMM
// C[b, m0:+128, n0:+128] = act( A[b] @ Wt[day[b]]^T + bias )
// A : [BB*TT, KDIM]  row-major (K contiguous), tf32 values
// Wt: [NDAYS, NTOT, KDIM]  (K contiguous), tf32 values
// 256 threads, 8 warps as 2(M) x 4(N); warp tile 64x32; 3-stage cp.async.
#define STAGES 3
#define STAGE_BYTES 32768   // A 16KB + B 16KB
#define SMEM_DYN (STAGES * STAGE_BYTES)

template<int KDIM, int NTOT, bool RELU>
__global__ __launch_bounds__(256, 2) void gemm_mma(
    const float* __restrict__ A,
    const float* __restrict__ Wt,
    const float* __restrict__ bias,
    const int*   __restrict__ day,
    float*       __restrict__ C)
{
    extern __shared__ char smem[];
    const uint32_t sbase = smem_u32(smem);

    const int tid  = threadIdx.x;
    const int lane = tid & 31;
    const int wid  = tid >> 5;
    const int wm   = wid & 1;    // 0..1  (M)
    const int wn   = wid >> 1;   // 0..3  (N)

    const int b  = blockIdx.x;
    const int m0 = blockIdx.y * 128;
    const int n0 = blockIdx.z * 128;
    const int d  = __ldg(day + b);

    const float* Arow = A  + (size_t)(b * TT + m0) * KDIM;
    const float* Brow = Wt + ((size_t)d * NTOT + n0) * KDIM;

    const int lrow = tid >> 3;   // 0..31
    const int lchk = tid & 7;    // 16B chunk within a 128B row

    constexpr int KT = KDIM / 32;

    // ---- stage loader: A tile [128][32] + B tile [128][32], xor-swizzled
    auto load_stage = [&](int s, int kt) {
        const uint32_t as = sbase + s * STAGE_BYTES;
        const uint32_t bs = as + 16384;
        const float* ag = Arow + kt * 32 + lchk * 4;
        const float* bg = Brow + kt * 32 + lchk * 4;
        #pragma unroll
        for (int p = 0; p < 4; p++) {
            const int row = p * 32 + lrow;
            const uint32_t soff = row * 128 + ((lchk ^ (row & 7)) << 4);
            cp16(as + soff, ag + (size_t)row * KDIM);
            cp16(bs + soff, bg + (size_t)row * KDIM);
        }
        asm volatile("cp.async.commit_group;" ::: "memory");
    };

    load_stage(0, 0);
    load_stage(1, 1);

    float acc[4][4][4] = {};

    // precomputed ldmatrix lane geometry
    const int amat = lane >> 3;                    // 0..3
    const int arow_l = (lane & 7) + ((amat & 1) << 3);
    const int achk_d = amat >> 1;                  // 0 or 1
    const int brow_l = (lane & 7) + (((lane >> 4) & 1) << 3);
    const int bchk_d = (lane >> 3) & 1;

    for (int i = 0; i < KT; i++) {
        if (i + 1 < KT) asm volatile("cp.async.wait_group 1;" ::: "memory");
        else            asm volatile("cp.async.wait_group 0;" ::: "memory");
        __syncthreads();
        if (i + 2 < KT) load_stage((i + 2) % STAGES, i + 2);

        const uint32_t as = sbase + (i % STAGES) * STAGE_BYTES;
        const uint32_t bs = as + 16384;

        #pragma unroll
        for (int ks = 0; ks < 4; ks++) {           // kk = ks*8 -> chunk base ks*2
            uint32_t af[4][4];
            #pragma unroll
            for (int mt = 0; mt < 4; mt++) {
                const int row = wm * 64 + mt * 16 + arow_l;
                const int chk = ks * 2 + achk_d;
                ldm4(af[mt][0], af[mt][1], af[mt][2], af[mt][3],
                     as + row * 128 + ((chk ^ (row & 7)) << 4));
            }
            uint32_t bf[2][4];
            #pragma unroll
            for (int ntp = 0; ntp < 2; ntp++) {
                const int row = wn * 32 + ntp * 16 + brow_l;
                const int chk = ks * 2 + bchk_d;
                ldm4(bf[ntp][0], bf[ntp][1], bf[ntp][2], bf[ntp][3],
                     bs + row * 128 + ((chk ^ (row & 7)) << 4));
            }
            #pragma unroll
            for (int mt = 0; mt < 4; mt++)
                #pragma unroll
                for (int nt = 0; nt < 4; nt++)
                    mma1688(acc[mt][nt], af[mt],
                            bf[nt >> 1][(nt & 1) * 2], bf[nt >> 1][(nt & 1) * 2 + 1]);
        }
    }

    // ---- epilogue: bias (+relu+rna)
    const int g   = lane >> 2;
    const int tig = lane & 3;
    const float* biasd = bias + (size_t)d * NTOT + n0 + wn * 32;
    float* Cb = C + (size_t)(b * TT + m0 + wm * 64) * NTOT + n0 + wn * 32;

    #pragma unroll
    for (int nt = 0; nt < 4; nt++) {
        const int coff = nt * 8 + tig * 2;
        const float2 bb = *(const float2*)(biasd + coff);
        #pragma unroll
        for (int mt = 0; mt < 4; mt++) {
            const int r0 = mt * 16 + g;
            float2 v0, v1;
            v0.x = acc[mt][nt][0] + bb.x;  v0.y = acc[mt][nt][1] + bb.y;
            v1.x = acc[mt][nt][2] + bb.x;  v1.y = acc[mt][nt][3] + bb.y;
            if (RELU) {
                v0.x = rna_tf32(fmaxf(v0.x, 0.0f)); v0.y = rna_tf32(fmaxf(v0.y, 0.0f));
                v1.x = rna_tf32(fmaxf(v1.x, 0.0f)); v1.y = rna_tf32(fmaxf(v1.y, 0.0f));
            }
            *(float2*)(Cb + (size_t)r0 * NTOT + coff)       = v0;
            *(float2*)(Cb + (size_t)(r0 + 8) * NTOT + coff) = v1;
        }
    }
}

// ---------------------------------------------------------------- LayerNorm
__global__ __launch_bounds__(256) void ln_kernel(
    float*       __restrict__ y,      // [B*T, D_OUT], in-place
    const float* __restrict__ gamma,
    const float* __restrict__ beta,
    const int*   __restrict__ day)
{
    const int row = blockIdx.x;
    const int b   = row / TT;
    const int d   = __ldg(day + b);
    float* yr = y + (size_t)row * DOUT;

    const int tid = threadIdx.x;
    const float2 v = *(const float2*)(yr + tid * 2);

    float s  = v.x + v.y;
    float sq = v.x * v.x + v.y * v.y;
    #pragma unroll
    for (int off = 16; off; off >>= 1) {
        s  += __shfl_xor_sync(0xffffffffu, s,  off);
        sq += __shfl_xor_sync(0xffffffffu, sq, off);
    }
    __shared__ float ss[8], sqs[8];
    const int w = tid >> 5, l = tid & 31;
    if (l == 0) { ss[w] = s; sqs[w] = sq; }
    __syncthreads();
    if (w == 0) {
        s  = (l < 8) ? ss[l]  : 0.0f;
        sq = (l < 8) ? sqs[l] : 0.0f;
        #pragma unroll
        for (int off = 16; off; off >>= 1) {
            s  += __shfl_xor_sync(0xffffffffu, s,  off);
            sq += __shfl_xor_sync(0xffffffffu, sq, off);
        }
        if (l == 0) { ss[0] = s; sqs[0] = sq; }
    }
    __syncthreads();
    s = ss[0]; sq = sqs[0];

    const float mean = s * (1.0f / DOUT);
    const float var  = sq * (1.0f / DOUT) - mean * mean;
    const float inv  = rsqrtf(var + EPS_);

    const float2 g2 = *(const float2*)(gamma + (size_t)d * DOUT + tid * 2);
    const float2 b2 = *(const float2*)(beta  + (size_t)d * DOUT + tid * 2);
    float2 o;
    o.x = (v.x - mean) * inv * g2.x + b2.x;
    o.y = (v.y - mean) * inv * g2.y + b2.y;
    *(float2*)(yr + tid * 2) = o;
}

// ---------------------------------------------------------------- launch
extern "C" void kernel_launch(void* const* d_in, const int* in_sizes, int n_in,
                              void* d_out, int out_size)
{
    const float* x     = (const float*)d_in[0];
    const int*   day   = (const int*)  d_in[1];
    const float* W1    = (const float*)d_in[2];
    const float* b1    = (const float*)d_in[3];
    const float* W2    = (const float*)d_in[4];
    const float* b2    = (const float*)d_in[5];
    const float* gamma = (const float*)d_in[6];
    const float* beta  = (const float*)d_in[7];
    float* out = (float*)d_out;

    float *xt, *h, *wt1, *wt2;
    cudaGetSymbolAddress((void**)&xt,  g_xt);
    cudaGetSymbolAddress((void**)&h,   g_h);
    cudaGetSymbolAddress((void**)&wt1, g_wt1);
    cudaGetSymbolAddress((void**)&wt2, g_wt2);

    // prep: RNA-convert x; transpose+RNA W1, W2
    const int n4 = BB * TT * DIN / 4;
    cvt_x_kernel<<<(n4 + 255) / 256, 256>>>((const float4*)x, (float4*)xt, n4);
    transpose_rna_kernel<DIN,  DHID><<<dim3(DHID / 32, DIN  / 32, NDAYS), dim3(32, 8)>>>(W1, wt1);
    transpose_rna_kernel<DHID, DOUT><<<dim3(DOUT / 32, DHID / 32, NDAYS), dim3(32, 8)>>>(W2, wt2);

    cudaFuncSetAttribute(gemm_mma<DIN,  DHID, true>,
                         cudaFuncAttributeMaxDynamicSharedMemorySize, SMEM_DYN);
    cudaFuncSetAttribute(gemm_mma<DHID, DOUT, false>,
                         cudaFuncAttributeMaxDynamicSharedMemorySize, SMEM_DYN);

    // GEMM1: xt @ W1^T -> h  (bias + relu + rna fused)
    gemm_mma<DIN,  DHID, true><<<dim3(BB, TT / 128, DHID / 128), 256, SMEM_DYN>>>(
        xt, wt1, b1, day, h);
    // GEMM2: h @ W2^T -> out (bias fused)
    gemm_mma<DHID, DOUT, false><<<dim3(BB, TT / 128, DOUT / 128), 256, SMEM_DYN>>>(
        h, wt2, b2, day, out);
    // LayerNorm in-place
    ln_kernel<<<BB * TT, 256>>>(out, gamma, beta, day);
}

// round 5
// speedup vs baseline: 6.3430x; 1.4269x over previous
#include <cuda_runtime.h>
#include <cuda_fp16.h>
#include <cstdint>

#define BB    64
#define TT    512
#define DIN   512
#define DHID  1024
#define DOUT  512
#define NDAYS 24
#define EPS_  1e-5f

// Scratch (__device__ globals; no runtime allocation).
__device__ __half g_xh [(size_t)BB * TT * DIN];       // 32 MB x -> fp16
__device__ __half g_h  [(size_t)BB * TT * DHID];      // 64 MB hidden fp16
__device__ __half g_wt1[(size_t)NDAYS * DHID * DIN];  // 24 MB W1^T [d][n][k] fp16
__device__ __half g_wt2[(size_t)NDAYS * DOUT * DHID]; // 24 MB W2^T [d][n][k] fp16

// ---------------------------------------------------------------- helpers
__device__ __forceinline__ uint32_t smem_u32(const void* p) {
    uint32_t a;
    asm("{ .reg .u64 t; cvta.to.shared.u64 t, %1; cvt.u32.u64 %0, t; }"
        : "=r"(a) : "l"(p));
    return a;
}
__device__ __forceinline__ void cp16(uint32_t dst, const void* src) {
    asm volatile("cp.async.cg.shared.global [%0], [%1], 16;"
                 :: "r"(dst), "l"(src) : "memory");
}
__device__ __forceinline__ void ldm4(uint32_t& r0, uint32_t& r1,
                                     uint32_t& r2, uint32_t& r3, uint32_t a) {
    asm volatile("ldmatrix.sync.aligned.m8n8.x4.shared.b16 {%0,%1,%2,%3}, [%4];"
                 : "=r"(r0), "=r"(r1), "=r"(r2), "=r"(r3) : "r"(a));
}
__device__ __forceinline__ void mma16816(float* c, const uint32_t* a,
                                         uint32_t b0, uint32_t b1) {
    asm volatile(
        "mma.sync.aligned.m16n8k16.row.col.f32.f16.f16.f32 "
        "{%0,%1,%2,%3}, {%4,%5,%6,%7}, {%8,%9}, {%0,%1,%2,%3};"
        : "+f"(c[0]), "+f"(c[1]), "+f"(c[2]), "+f"(c[3])
        : "r"(a[0]), "r"(a[1]), "r"(a[2]), "r"(a[3]), "r"(b0), "r"(b1));
}

// ---------------------------------------------------------------- prep passes
// x fp32 -> fp16 (RNE). 8 elements per thread.
__global__ __launch_bounds__(256) void cvt_x_kernel(const float4* __restrict__ in,
                                                    __half2* __restrict__ out, int n8) {
    int i = blockIdx.x * blockDim.x + threadIdx.x;
    if (i < n8) {
        float4 v0 = in[i * 2], v1 = in[i * 2 + 1];
        out[i * 4 + 0] = __floats2half2_rn(v0.x, v0.y);
        out[i * 4 + 1] = __floats2half2_rn(v0.z, v0.w);
        out[i * 4 + 2] = __floats2half2_rn(v1.x, v1.y);
        out[i * 4 + 3] = __floats2half2_rn(v1.z, v1.w);
    }
}

// W [NDAYS][K][N] fp32 -> Wt [NDAYS][N][K] fp16 (RNE).
template<int K, int N>
__global__ __launch_bounds__(256) void transpose_h_kernel(const float* __restrict__ W,
                                                          __half* __restrict__ Wt) {
    __shared__ float t[32][33];
    const int d  = blockIdx.z;
    const int n0 = blockIdx.x * 32;
    const int k0 = blockIdx.y * 32;
    const float* Wd  = W  + (size_t)d * K * N;
    __half*      Wtd = Wt + (size_t)d * N * K;
    const int tx = threadIdx.x, ty = threadIdx.y;  // 32 x 8
    #pragma unroll
    for (int r = 0; r < 32; r += 8)
        t[ty + r][tx] = Wd[(size_t)(k0 + ty + r) * N + n0 + tx];
    __syncthreads();
    #pragma unroll
    for (int r = 0; r < 32; r += 8)
        Wtd[(size_t)(n0 + ty + r) * K + k0 + tx] = __float2half_rn(t[tx][ty + r]);
}

// ---------------------------------------------------------------- FP16 GEMM
// C[b, m0:+128, n0:+128] = act( A[b] @ Wt[day[b]]^T + bias )
// A : [BB*TT, KDIM] fp16 (K contiguous).  Wt: [NDAYS, NTOT, KDIM] fp16.
// 256 threads, 8 warps as 2(M) x 4(N); warp tile 64x32.
// K-chunk = 64 (4 x k16 MMA steps), 3-stage cp.async pipeline.
#define STAGES 3
#define STAGE_BYTES 32768   // A 16KB + B 16KB  (128 rows x 128B each)
#define SMEM_DYN (STAGES * STAGE_BYTES)

template<int KDIM, int NTOT, bool RELU, typename CT>
__global__ __launch_bounds__(256, 2) void gemm_mma(
    const __half* __restrict__ A,
    const __half* __restrict__ Wt,
    const float*  __restrict__ bias,
    const int*    __restrict__ day,
    CT*           __restrict__ C)
{
    extern __shared__ char smem[];
    const uint32_t sbase = smem_u32(smem);

    const int tid  = threadIdx.x;
    const int lane = tid & 31;
    const int wid  = tid >> 5;
    const int wm   = wid & 1;    // 0..1  (M)
    const int wn   = wid >> 1;   // 0..3  (N)

    const int b  = blockIdx.x;
    const int m0 = blockIdx.y * 128;
    const int n0 = blockIdx.z * 128;
    const int d  = __ldg(day + b);

    const __half* Arow = A  + (size_t)(b * TT + m0) * KDIM;
    const __half* Brow = Wt + ((size_t)d * NTOT + n0) * KDIM;

    const int lrow = tid >> 3;   // 0..31
    const int lchk = tid & 7;    // 16B chunk within a 128B (64-half) row

    constexpr int KT = KDIM / 64;

    // ---- stage loader: A tile [128][64]h + B tile [128][64]h, xor-swizzled
    auto load_stage = [&](int s, int kt) {
        const uint32_t as = sbase + s * STAGE_BYTES;
        const uint32_t bs = as + 16384;
        const __half* ag = Arow + kt * 64 + lchk * 8;
        const __half* bg = Brow + kt * 64 + lchk * 8;
        #pragma unroll
        for (int p = 0; p < 4; p++) {
            const int row = p * 32 + lrow;
            const uint32_t soff = row * 128 + ((lchk ^ (row & 7)) << 4);
            cp16(as + soff, ag + (size_t)row * KDIM);
            cp16(bs + soff, bg + (size_t)row * KDIM);
        }
        asm volatile("cp.async.commit_group;" ::: "memory");
    };

    load_stage(0, 0);
    load_stage(1, 1);

    float acc[4][4][4] = {};

    // ldmatrix lane geometry (identical for A and B tiles):
    // row = base + (lane & 15), k-octet select = lane >> 4
    const int lrow16 = lane & 15;
    const int lhi    = lane >> 4;      // 0 or 1

    for (int i = 0; i < KT; i++) {
        if (i + 1 < KT) asm volatile("cp.async.wait_group 1;" ::: "memory");
        else            asm volatile("cp.async.wait_group 0;" ::: "memory");
        __syncthreads();
        if (i + 2 < KT) load_stage((i + 2) % STAGES, i + 2);

        const uint32_t as = sbase + (i % STAGES) * STAGE_BYTES;
        const uint32_t bs = as + 16384;

        #pragma unroll
        for (int ks = 0; ks < 4; ks++) {          // k16 step; chunks 2ks, 2ks+1
            const int chk = 2 * ks + lhi;
            uint32_t af[4][4];
            #pragma unroll
            for (int mt = 0; mt < 4; mt++) {
                const int row = wm * 64 + mt * 16 + lrow16;
                ldm4(af[mt][0], af[mt][1], af[mt][2], af[mt][3],
                     as + row * 128 + ((chk ^ (row & 7)) << 4));
            }
            uint32_t bf[2][4];
            #pragma unroll
            for (int ntp = 0; ntp < 2; ntp++) {
                const int row = wn * 32 + ntp * 16 + lrow16;
                ldm4(bf[ntp][0], bf[ntp][1], bf[ntp][2], bf[ntp][3],
                     bs + row * 128 + ((chk ^ (row & 7)) << 4));
            }
            // bf[p]: r0=(n0-7,k0-7) r1=(n8-15,k0-7) r2=(n0-7,k8-15) r3=(n8-15,k8-15)
            #pragma unroll
            for (int mt = 0; mt < 4; mt++)
                #pragma unroll
                for (int nt = 0; nt < 4; nt++)
                    mma16816(acc[mt][nt], af[mt],
                             bf[nt >> 1][nt & 1], bf[nt >> 1][2 + (nt & 1)]);
        }
    }

    // ---- epilogue: bias (+relu), fp16 or fp32 output
    const int g   = lane >> 2;
    const int tig = lane & 3;
    const float* biasd = bias + (size_t)d * NTOT + n0 + wn * 32;
    CT* Cb = C + (size_t)(b * TT + m0 + wm * 64) * NTOT + n0 + wn * 32;

    #pragma unroll
    for (int nt = 0; nt < 4; nt++) {
        const int coff = nt * 8 + tig * 2;
        const float2 bb = *(const float2*)(biasd + coff);
        #pragma unroll
        for (int mt = 0; mt < 4; mt++) {
            const int r0 = mt * 16 + g;
            float2 v0, v1;
            v0.x = acc[mt][nt][0] + bb.x;  v0.y = acc[mt][nt][1] + bb.y;
            v1.x = acc[mt][nt][2] + bb.x;  v1.y = acc[mt][nt][3] + bb.y;
            if (RELU) {
                v0.x = fmaxf(v0.x, 0.0f); v0.y = fmaxf(v0.y, 0.0f);
                v1.x = fmaxf(v1.x, 0.0f); v1.y = fmaxf(v1.y, 0.0f);
            }
            if constexpr (sizeof(CT) == 2) {
                *(__half2*)((__half*)Cb + (size_t)r0 * NTOT + coff) =
                    __floats2half2_rn(v0.x, v0.y);
                *(__half2*)((__half*)Cb + (size_t)(r0 + 8) * NTOT + coff) =
                    __floats2half2_rn(v1.x, v1.y);
            } else {
                *(float2*)((float*)Cb + (size_t)r0 * NTOT + coff)       = v0;
                *(float2*)((float*)Cb + (size_t)(r0 + 8) * NTOT + coff) = v1;
            }
        }
    }
}

// ---------------------------------------------------------------- LayerNorm
__global__ __launch_bounds__(256) void ln_kernel(
    float*       __restrict__ y,      // [B*T, D_OUT], in-place
    const float* __restrict__ gamma,
    const float* __restrict__ beta,
    const int*   __restrict__ day)
{
    const int row = blockIdx.x;
    const int b   = row / TT;
    const int d   = __ldg(day + b);
    float* yr = y + (size_t)row * DOUT;

    const int tid = threadIdx.x;
    const float2 v = *(const float2*)(yr + tid * 2);

    float s  = v.x + v.y;
    float sq = v.x * v.x + v.y * v.y;
    #pragma unroll
    for (int off = 16; off; off >>= 1) {
        s  += __shfl_xor_sync(0xffffffffu, s,  off);
        sq += __shfl_xor_sync(0xffffffffu, sq, off);
    }
    __shared__ float ss[8], sqs[8];
    const int w = tid >> 5, l = tid & 31;
    if (l == 0) { ss[w] = s; sqs[w] = sq; }
    __syncthreads();
    if (w == 0) {
        s  = (l < 8) ? ss[l]  : 0.0f;
        sq = (l < 8) ? sqs[l] : 0.0f;
        #pragma unroll
        for (int off = 16; off; off >>= 1) {
            s  += __shfl_xor_sync(0xffffffffu, s,  off);
            sq += __shfl_xor_sync(0xffffffffu, sq, off);
        }
        if (l == 0) { ss[0] = s; sqs[0] = sq; }
    }
    __syncthreads();
    s = ss[0]; sq = sqs[0];

    const float mean = s * (1.0f / DOUT);
    const float var  = sq * (1.0f / DOUT) - mean * mean;
    const float inv  = rsqrtf(var + EPS_);

    const float2 g2 = *(const float2*)(gamma + (size_t)d * DOUT + tid * 2);
    const float2 b2 = *(const float2*)(beta  + (size_t)d * DOUT + tid * 2);
    float2 o;
    o.x = (v.x - mean) * inv * g2.x + b2.x;
    o.y = (v.y - mean) * inv * g2.y + b2.y;
    *(float2*)(yr + tid * 2) = o;
}

// ---------------------------------------------------------------- launch
extern "C" void kernel_launch(void* const* d_in, const int* in_sizes, int n_in,
                              void* d_out, int out_size)
{
    const float* x     = (const float*)d_in[0];
    const int*   day   = (const int*)  d_in[1];
    const float* W1    = (const float*)d_in[2];
    const float* b1    = (const float*)d_in[3];
    const float* W2    = (const float*)d_in[4];
    const float* b2    = (const float*)d_in[5];
    const float* gamma = (const float*)d_in[6];
    const float* beta  = (const float*)d_in[7];
    float* out = (float*)d_out;

    __half *xh, *h, *wt1, *wt2;
    cudaGetSymbolAddress((void**)&xh,  g_xh);
    cudaGetSymbolAddress((void**)&h,   g_h);
    cudaGetSymbolAddress((void**)&wt1, g_wt1);
    cudaGetSymbolAddress((void**)&wt2, g_wt2);

    // prep: convert x to fp16; transpose+convert W1, W2
    const int n8 = BB * TT * DIN / 8;
    cvt_x_kernel<<<(n8 + 255) / 256, 256>>>((const float4*)x, (__half2*)xh, n8);
    transpose_h_kernel<DIN,  DHID><<<dim3(DHID / 32, DIN  / 32, NDAYS), dim3(32, 8)>>>(W1, wt1);
    transpose_h_kernel<DHID, DOUT><<<dim3(DOUT / 32, DHID / 32, NDAYS), dim3(32, 8)>>>(W2, wt2);

    cudaFuncSetAttribute(gemm_mma<DIN,  DHID, true,  __half>,
                         cudaFuncAttributeMaxDynamicSharedMemorySize, SMEM_DYN);
    cudaFuncSetAttribute(gemm_mma<DHID, DOUT, false, float>,
                         cudaFuncAttributeMaxDynamicSharedMemorySize, SMEM_DYN);

    // GEMM1: xh @ W1^T -> h (fp16, bias+relu fused)
    gemm_mma<DIN,  DHID, true,  __half><<<dim3(BB, TT / 128, DHID / 128), 256, SMEM_DYN>>>(
        xh, wt1, b1, day, h);
    // GEMM2: h @ W2^T -> out (fp32, bias fused)
    gemm_mma<DHID, DOUT, false, float><<<dim3(BB, TT / 128, DOUT / 128), 256, SMEM_DYN>>>(
        h, wt2, b2, day, out);
    // LayerNorm in-place
    ln_kernel<<<BB * TT, 256>>>(out, gamma, beta, day);
}